// round 1
// baseline (speedup 1.0000x reference)
#include <cuda_runtime.h>
#include <math.h>

#define BB    2
#define SS    2048
#define DD    512
#define HH    8
#define DHH   64
#define INNER 512
#define MTOT  (BB*SS)      // 4096
#define NQKV  (3*INNER)    // 1536

// Scratch (static device globals; no allocation in kernel_launch)
__device__ float g_scale[2];
__device__ float g_Q[BB*HH*SS*DHH];
__device__ float g_K[BB*HH*SS*DHH];
__device__ float g_V[BB*HH*SS*DHH];
__device__ float g_O[(size_t)MTOT*INNER];

// ---------------------------------------------------------------------------
// Spectral-norm scale:  scale = sigma * ||W u|| / ||W^T W u||
// (identical math to one power-iteration step: sigma_w = ||W^T (Wu/||Wu||)||)
// ---------------------------------------------------------------------------
__global__ void sn_scale_kernel(const float* __restrict__ W, const float* __restrict__ u,
                                const float* __restrict__ sigma, int R, int C, int out_idx)
{
    __shared__ float t[1536];
    __shared__ float red[512];
    const int tid = threadIdx.x;   // 512 threads

    // t = W u
    for (int r = tid; r < R; r += 512) {
        const float* Wr = W + (size_t)r * C;
        float acc = 0.f;
        for (int c = 0; c < C; ++c) acc += Wr[c] * u[c];
        t[r] = acc;
    }
    __syncthreads();

    // tt = ||t||^2
    float loc = 0.f;
    for (int r = tid; r < R; r += 512) loc += t[r] * t[r];
    red[tid] = loc;
    __syncthreads();
    for (int s = 256; s > 0; s >>= 1) {
        if (tid < s) red[tid] += red[tid + s];
        __syncthreads();
    }
    const float tt = red[0];
    __syncthreads();

    // ss = ||W^T t||^2  (thread per column, coalesced over columns)
    float sc = 0.f;
    if (tid < C) {
        float acc = 0.f;
        for (int r = 0; r < R; ++r) acc += W[(size_t)r * C + tid] * t[r];
        sc = acc * acc;
    }
    red[tid] = sc;
    __syncthreads();
    for (int s = 256; s > 0; s >>= 1) {
        if (tid < s) red[tid] += red[tid + s];
        __syncthreads();
    }
    if (tid == 0) g_scale[out_idx] = sigma[0] * sqrtf(tt / red[0]);
}

// ---------------------------------------------------------------------------
// C[m,n] = scale * sum_k A[m,k] * Wt[n,k]   (both K-major, "NT" gemm)
// EPI=0: scatter into g_Q/g_K/g_V as [B][H][S][Dh]
// EPI=1: Cout[m*N+n] = val + bias[n]   (A taken from g_O)
// Block tile 64x64, 256 threads, 4x4 per thread, K-step 16.
// ---------------------------------------------------------------------------
template<int EPI>
__global__ __launch_bounds__(256) void gemm_nt_kernel(const float* __restrict__ Ain,
                                                      const float* __restrict__ Wt,
                                                      const float* __restrict__ bias,
                                                      float* __restrict__ Cout,
                                                      int Mdim, int Ndim, int Kdim, int scale_idx)
{
    __shared__ float As[16][68];
    __shared__ float Bs[16][68];

    const float* A = (EPI == 1) ? (const float*)g_O : Ain;

    const int m0 = blockIdx.y * 64;
    const int n0 = blockIdx.x * 64;
    const int tid = threadIdx.x;
    const int lm = tid >> 2;            // 0..63 load row
    const int lk = (tid & 3) * 4;       // 0,4,8,12 k-quad
    const int tm = (tid >> 4) * 4;      // compute m offset
    const int tn = (tid & 15) * 4;      // compute n offset (fast across lanes)

    float acc[4][4] = {};

    for (int k0 = 0; k0 < Kdim; k0 += 16) {
        float4 a4 = *(const float4*)(A  + (size_t)(m0 + lm) * Kdim + k0 + lk);
        float4 b4 = *(const float4*)(Wt + (size_t)(n0 + lm) * Kdim + k0 + lk);
        As[lk + 0][lm] = a4.x; As[lk + 1][lm] = a4.y; As[lk + 2][lm] = a4.z; As[lk + 3][lm] = a4.w;
        Bs[lk + 0][lm] = b4.x; Bs[lk + 1][lm] = b4.y; Bs[lk + 2][lm] = b4.z; Bs[lk + 3][lm] = b4.w;
        __syncthreads();
        #pragma unroll
        for (int k = 0; k < 16; ++k) {
            float4 av = *(const float4*)&As[k][tm];
            float4 bv = *(const float4*)&Bs[k][tn];
            float a[4] = {av.x, av.y, av.z, av.w};
            float b[4] = {bv.x, bv.y, bv.z, bv.w};
            #pragma unroll
            for (int i = 0; i < 4; ++i)
                #pragma unroll
                for (int j = 0; j < 4; ++j)
                    acc[i][j] += a[i] * b[j];
        }
        __syncthreads();
    }

    const float sc = g_scale[scale_idx];

    if (EPI == 0) {
        #pragma unroll
        for (int i = 0; i < 4; ++i) {
            const int m = m0 + tm + i;
            const int n = n0 + tn;
            const int seg  = n >> 9;      // 0:q 1:k 2:v
            const int nn   = n & 511;
            const int head = nn >> 6;
            const int d    = nn & 63;
            const int b    = m >> 11;
            const int s    = m & 2047;
            float* dst = (seg == 0) ? g_Q : (seg == 1) ? g_K : g_V;
            float4 v;
            v.x = acc[i][0] * sc; v.y = acc[i][1] * sc;
            v.z = acc[i][2] * sc; v.w = acc[i][3] * sc;
            *(float4*)(dst + (((size_t)(b * HH + head) * SS + s) * DHH + d)) = v;
        }
    } else {
        #pragma unroll
        for (int i = 0; i < 4; ++i) {
            const int m = m0 + tm + i;
            const int n = n0 + tn;
            float4 bb = *(const float4*)(bias + n);
            float4 v;
            v.x = acc[i][0] * sc + bb.x; v.y = acc[i][1] * sc + bb.y;
            v.z = acc[i][2] * sc + bb.z; v.w = acc[i][3] * sc + bb.w;
            *(float4*)(Cout + (size_t)m * Ndim + n) = v;
        }
    }
}

// ---------------------------------------------------------------------------
// Attention: one query row per thread (q,o in registers), online softmax over
// all 2048 keys, K/V tiles (64 keys) staged in smem and broadcast-read.
// Mask: scores for j in [row-7, row] set to -3.4e38 (reference masks the
// causal band INSIDE the window — softmax runs over everything else).
// Writes O directly in [B][S][H*Dh] layout for the output GEMM.
// ---------------------------------------------------------------------------
__global__ __launch_bounds__(128) void attn_kernel(const float* __restrict__ temperature)
{
    __shared__ float4 Ks[64 * 16];
    __shared__ float4 Vs[64 * 16];

    const int bh  = blockIdx.x;                       // 0..15
    const int row = blockIdx.y * 128 + threadIdx.x;   // query index
    const float tscale = expf(temperature[0]);

    const float* Qb = g_Q + (size_t)bh * SS * DHH;
    const float4* Kb4 = (const float4*)(g_K + (size_t)bh * SS * DHH);
    const float4* Vb4 = (const float4*)(g_V + (size_t)bh * SS * DHH);

    float q[64];
    {
        const float4* q4 = (const float4*)(Qb + (size_t)row * DHH);
        #pragma unroll
        for (int i = 0; i < 16; ++i) {
            float4 v = q4[i];
            q[4*i+0] = v.x * tscale; q[4*i+1] = v.y * tscale;
            q[4*i+2] = v.z * tscale; q[4*i+3] = v.w * tscale;
        }
    }

    float o[64];
    #pragma unroll
    for (int d = 0; d < 64; ++d) o[d] = 0.f;
    float mrun = -3.3e38f;   // > mask value so fully-masked chunks give p=exp(-1e37)=0
    float lrun = 0.f;

    for (int jt = 0; jt < SS; jt += 64) {
        __syncthreads();
        const float4* Kg = Kb4 + (size_t)jt * 16;
        const float4* Vg = Vb4 + (size_t)jt * 16;
        #pragma unroll
        for (int it = 0; it < 8; ++it) {
            const int idx = threadIdx.x + it * 128;
            Ks[idx] = Kg[idx];
            Vs[idx] = Vg[idx];
        }
        __syncthreads();

        #pragma unroll 1
        for (int jc = 0; jc < 64; jc += 8) {
            float sv[8];
            #pragma unroll
            for (int jj = 0; jj < 8; ++jj) {
                const float4* kr = &Ks[(jc + jj) * 16];
                float acc = 0.f;
                #pragma unroll
                for (int d4 = 0; d4 < 16; ++d4) {
                    float4 kv = kr[d4];
                    acc += q[4*d4+0] * kv.x + q[4*d4+1] * kv.y
                         + q[4*d4+2] * kv.z + q[4*d4+3] * kv.w;
                }
                const int j = jt + jc + jj;
                const bool masked = (j <= row) && (j >= row - 7);
                sv[jj] = masked ? -3.4e38f : acc;
            }
            float mc = sv[0];
            #pragma unroll
            for (int jj = 1; jj < 8; ++jj) mc = fmaxf(mc, sv[jj]);
            const float mnew = fmaxf(mrun, mc);
            const float corr = __expf(mrun - mnew);
            lrun *= corr;
            #pragma unroll
            for (int d = 0; d < 64; ++d) o[d] *= corr;
            mrun = mnew;
            #pragma unroll
            for (int jj = 0; jj < 8; ++jj) {
                const float p = __expf(sv[jj] - mnew);
                lrun += p;
                const float4* vr = &Vs[(jc + jj) * 16];
                #pragma unroll
                for (int d4 = 0; d4 < 16; ++d4) {
                    float4 vv = vr[d4];
                    o[4*d4+0] += p * vv.x; o[4*d4+1] += p * vv.y;
                    o[4*d4+2] += p * vv.z; o[4*d4+3] += p * vv.w;
                }
            }
        }
    }

    const float inv = 1.f / lrun;
    const int b = bh >> 3, h = bh & 7;
    float4* Op4 = (float4*)(g_O + ((size_t)(b * SS + row) * INNER + h * DHH));
    #pragma unroll
    for (int i = 0; i < 16; ++i) {
        float4 v;
        v.x = o[4*i+0] * inv; v.y = o[4*i+1] * inv;
        v.z = o[4*i+2] * inv; v.w = o[4*i+3] * inv;
        Op4[i] = v;
    }
}

// ---------------------------------------------------------------------------
extern "C" void kernel_launch(void* const* d_in, const int* in_sizes, int n_in,
                              void* d_out, int out_size)
{
    const float* x      = (const float*)d_in[0];
    const float* W_qkv  = (const float*)d_in[1];
    const float* u_qkv  = (const float*)d_in[2];
    const float* sg_qkv = (const float*)d_in[3];
    const float* W_out  = (const float*)d_in[4];
    const float* b_out  = (const float*)d_in[5];
    const float* u_out  = (const float*)d_in[6];
    const float* sg_out = (const float*)d_in[7];
    const float* temp   = (const float*)d_in[8];
    float* out = (float*)d_out;

    sn_scale_kernel<<<1, 512>>>(W_qkv, u_qkv, sg_qkv, NQKV, DD, 0);
    sn_scale_kernel<<<1, 512>>>(W_out, u_out, sg_out, INNER, DD, 1);
    gemm_nt_kernel<0><<<dim3(NQKV / 64, MTOT / 64), 256>>>(x, W_qkv, nullptr, nullptr,
                                                           MTOT, NQKV, DD, 0);
    attn_kernel<<<dim3(BB * HH, SS / 128), 128>>>(temp);
    gemm_nt_kernel<1><<<dim3(DD / 64, MTOT / 64), 256>>>(nullptr, W_out, b_out, out,
                                                         MTOT, DD, INNER, 1);
}

// round 3
// speedup vs baseline: 1.9045x; 1.9045x over previous
#include <cuda_runtime.h>
#include <math.h>
#include <stdint.h>

#define BB    2
#define SS    2048
#define DD    512
#define HH    8
#define DHH   64
#define INNER 512
#define MTOT  (BB*SS)      // 4096
#define NQKV  (3*INNER)    // 1536

// ---------------- scratch ----------------
__device__ float g_scale[2];
__device__ float g_tt[2];
__device__ float g_ss[2];
__device__ float g_t[NQKV];
__device__ float g_Q[BB*HH*SS*DHH];
__device__ float g_K[BB*HH*SS*DHH];
__device__ float g_V[BB*HH*SS*DHH];
__device__ float g_O[(size_t)MTOT*INNER];

// ---------------- helpers ----------------
__device__ __forceinline__ uint32_t f2tf32(float f) {
    uint32_t r;
    asm("cvt.rna.tf32.f32 %0, %1;" : "=r"(r) : "f"(f));
    return r;
}

__device__ __forceinline__ void mma_tf32(float* d, const uint32_t* a, const uint32_t* b) {
    asm volatile("mma.sync.aligned.m16n8k8.row.col.f32.tf32.tf32.f32 "
                 "{%0,%1,%2,%3}, {%4,%5,%6,%7}, {%8,%9}, {%0,%1,%2,%3};"
                 : "+f"(d[0]), "+f"(d[1]), "+f"(d[2]), "+f"(d[3])
                 : "r"(a[0]), "r"(a[1]), "r"(a[2]), "r"(a[3]), "r"(b[0]), "r"(b[1]));
}

// f32x2 packed math
#define FMA2(d, a, b, c) asm("fma.rn.f32x2 %0, %1, %2, %3;" : "=l"(d) : "l"(a), "l"(b), "l"(c))
#define MUL2(d, a, b)    asm("mul.rn.f32x2 %0, %1, %2;" : "=l"(d) : "l"(a), "l"(b))
#define PACK2(o, x, y)   asm("mov.b64 %0, {%1, %2};" : "=l"(o) : "r"(__float_as_uint(x)), "r"(__float_as_uint(y)))
#define UNPK2(lo, hi, v) asm("mov.b64 {%0, %1}, %2;" : "=r"(lo), "=r"(hi) : "l"(v))

// ---------------------------------------------------------------------------
// Spectral-norm scale = sigma * ||W u|| / ||W^T W u||
// ---------------------------------------------------------------------------
__global__ void sn_zero_kernel() {
    if (threadIdx.x < 2) { g_tt[threadIdx.x] = 0.f; g_ss[threadIdx.x] = 0.f; }
}

__global__ void sn1_kernel(const float* __restrict__ W, const float* __restrict__ u,
                           int C, int idx) {
    const int w = threadIdx.x >> 5, lane = threadIdx.x & 31;
    const int r = blockIdx.x * 8 + w;
    const float* Wr = W + (size_t)r * C;
    float acc = 0.f;
    for (int c = lane; c < C; c += 32) acc += Wr[c] * u[c];
    #pragma unroll
    for (int s = 16; s > 0; s >>= 1) acc += __shfl_xor_sync(0xFFFFFFFF, acc, s);
    if (lane == 0) { g_t[r] = acc; atomicAdd(&g_tt[idx], acc * acc); }
}

__global__ void sn2_kernel(const float* __restrict__ W, int R, int C, int idx) {
    __shared__ float red[256];
    const int t = threadIdx.x;
    const int c = blockIdx.x * 64 + (t & 63);
    const int seg = t >> 6;
    float acc = 0.f;
    for (int r = seg; r < R; r += 4) acc += W[(size_t)r * C + c] * g_t[r];
    red[t] = acc;
    __syncthreads();
    if (seg == 0) {
        float s = red[t] + red[t + 64] + red[t + 128] + red[t + 192];
        atomicAdd(&g_ss[idx], s * s);
    }
}

__global__ void sn_fin_kernel(const float* __restrict__ s0, const float* __restrict__ s1) {
    if (threadIdx.x == 0) g_scale[0] = s0[0] * sqrtf(g_tt[0] / g_ss[0]);
    if (threadIdx.x == 1) g_scale[1] = s1[0] * sqrtf(g_tt[1] / g_ss[1]);
}

// ---------------------------------------------------------------------------
// tf32 mma.sync GEMM: C[m,n] = scale * sum_k A[m,k] * Wt[n,k]   (NT)
// Block tile 128x128, 256 threads = 8 warps as 2(M)x4(N); warp tile 64x32
// (4x4 grid of m16n8k8). K-chunk 32 staged in smem (stride 36 for banks).
// EPI=0: scatter into g_Q/g_K/g_V.  EPI=1: + bias into Cout (A from g_O).
// ---------------------------------------------------------------------------
#define SASTRIDE 36

template<int EPI>
__global__ __launch_bounds__(256) void gemm_mma_kernel(const float* __restrict__ Ain,
                                                       const float* __restrict__ Wt,
                                                       const float* __restrict__ bias,
                                                       float* __restrict__ Cout,
                                                       int Ndim, int Kdim, int sidx)
{
    __shared__ uint32_t sA[128 * SASTRIDE];
    __shared__ uint32_t sB[128 * SASTRIDE];

    const float* A = (EPI == 1) ? (const float*)g_O : Ain;
    const int tid = threadIdx.x;
    const int wid = tid >> 5, lane = tid & 31;
    const int g = lane >> 2, t = lane & 3;        // fragment row-group / quad
    const int wm = (wid >> 2) * 64;               // warp M offset
    const int wn = (wid & 3) * 32;                // warp N offset
    const int m0 = blockIdx.y * 128, n0 = blockIdx.x * 128;

    float acc[4][4][4];
    #pragma unroll
    for (int i = 0; i < 4; ++i)
        #pragma unroll
        for (int j = 0; j < 4; ++j)
            #pragma unroll
            for (int r = 0; r < 4; ++r) acc[i][j][r] = 0.f;

    for (int k0 = 0; k0 < Kdim; k0 += 32) {
        __syncthreads();
        #pragma unroll
        for (int p = 0; p < 4; ++p) {
            const int lin = tid + p * 256;        // 1024 float4 slots
            const int row = lin >> 3, q = lin & 7;
            float4 av = *(const float4*)(A  + (size_t)(m0 + row) * Kdim + k0 + q * 4);
            float4 bv = *(const float4*)(Wt + (size_t)(n0 + row) * Kdim + k0 + q * 4);
            uint4 at = make_uint4(f2tf32(av.x), f2tf32(av.y), f2tf32(av.z), f2tf32(av.w));
            uint4 bt = make_uint4(f2tf32(bv.x), f2tf32(bv.y), f2tf32(bv.z), f2tf32(bv.w));
            *(uint4*)&sA[row * SASTRIDE + q * 4] = at;
            *(uint4*)&sB[row * SASTRIDE + q * 4] = bt;
        }
        __syncthreads();

        #pragma unroll
        for (int ks = 0; ks < 4; ++ks) {
            const int k = ks * 8;
            uint32_t af[4][4], bf[4][2];
            #pragma unroll
            for (int mt = 0; mt < 4; ++mt) {
                const int r0 = wm + mt * 16;
                af[mt][0] = sA[(r0 + g    ) * SASTRIDE + k + t    ];
                af[mt][1] = sA[(r0 + g + 8) * SASTRIDE + k + t    ];
                af[mt][2] = sA[(r0 + g    ) * SASTRIDE + k + t + 4];
                af[mt][3] = sA[(r0 + g + 8) * SASTRIDE + k + t + 4];
            }
            #pragma unroll
            for (int nt = 0; nt < 4; ++nt) {
                const int c0 = wn + nt * 8;
                bf[nt][0] = sB[(c0 + g) * SASTRIDE + k + t    ];
                bf[nt][1] = sB[(c0 + g) * SASTRIDE + k + t + 4];
            }
            #pragma unroll
            for (int mt = 0; mt < 4; ++mt)
                #pragma unroll
                for (int nt = 0; nt < 4; ++nt)
                    mma_tf32(acc[mt][nt], af[mt], bf[nt]);
        }
    }

    const float sc = g_scale[sidx];

    #pragma unroll
    for (int mt = 0; mt < 4; ++mt) {
        #pragma unroll
        for (int half = 0; half < 2; ++half) {
            const int m = m0 + wm + mt * 16 + g + half * 8;
            #pragma unroll
            for (int nt = 0; nt < 4; ++nt) {
                const int n = n0 + wn + nt * 8 + 2 * t;
                const float v0 = acc[mt][nt][half * 2 + 0] * sc;
                const float v1 = acc[mt][nt][half * 2 + 1] * sc;
                if (EPI == 0) {
                    const int seg = n >> 9, nn = n & 511;
                    const int head = nn >> 6, d = nn & 63;
                    const int b = m >> 11, s = m & 2047;
                    float* dst = (seg == 0) ? g_Q : (seg == 1) ? g_K : g_V;
                    float2 v = make_float2(v0, v1);
                    *(float2*)(dst + (((size_t)(b * HH + head) * SS + s) * DHH + d)) = v;
                } else {
                    float2 bb = *(const float2*)(bias + n);
                    float2 v = make_float2(v0 + bb.x, v1 + bb.y);
                    *(float2*)(Cout + (size_t)m * Ndim + n) = v;
                }
            }
        }
    }
}

// ---------------------------------------------------------------------------
// Attention with packed f32x2 math. One query row per thread; online softmax
// over all 2048 keys; mask removes the causal band j in [row-7, row].
// ---------------------------------------------------------------------------
__global__ __launch_bounds__(128) void attn_kernel(const float* __restrict__ temperature)
{
    __shared__ ulonglong2 Ks[64 * 16];   // 64 keys x 64 floats (16 KB)
    __shared__ ulonglong2 Vs[64 * 16];

    const int bh  = blockIdx.x;
    const int row = blockIdx.y * 128 + threadIdx.x;
    const float tscale = expf(temperature[0]);

    const ulonglong2* Qb = (const ulonglong2*)(g_Q + (size_t)bh * SS * DHH);
    const ulonglong2* Kb = (const ulonglong2*)(g_K + (size_t)bh * SS * DHH);
    const ulonglong2* Vb = (const ulonglong2*)(g_V + (size_t)bh * SS * DHH);

    unsigned long long q2[32];
    {
        unsigned long long tp; PACK2(tp, tscale, tscale);
        const ulonglong2* qr = Qb + (size_t)row * 16;
        #pragma unroll
        for (int i = 0; i < 16; ++i) {
            ulonglong2 v = qr[i];
            MUL2(q2[2*i+0], v.x, tp);
            MUL2(q2[2*i+1], v.y, tp);
        }
    }

    unsigned long long o2[32];
    #pragma unroll
    for (int i = 0; i < 32; ++i) o2[i] = 0ULL;
    float mrun = -3.3e38f;
    float lrun = 0.f;

    for (int jt = 0; jt < SS; jt += 64) {
        __syncthreads();
        const ulonglong2* Kg = Kb + (size_t)jt * 16;
        const ulonglong2* Vg = Vb + (size_t)jt * 16;
        #pragma unroll
        for (int it = 0; it < 8; ++it) {
            const int idx = threadIdx.x + it * 128;
            Ks[idx] = Kg[idx];
            Vs[idx] = Vg[idx];
        }
        __syncthreads();

        #pragma unroll 1
        for (int jc = 0; jc < 64; jc += 8) {
            float sv[8];
            #pragma unroll
            for (int jj = 0; jj < 8; ++jj) {
                const ulonglong2* kr = &Ks[(jc + jj) * 16];
                unsigned long long a0 = 0ULL, a1 = 0ULL;
                #pragma unroll
                for (int i = 0; i < 16; ++i) {
                    ulonglong2 kv = kr[i];
                    FMA2(a0, q2[2*i+0], kv.x, a0);
                    FMA2(a1, q2[2*i+1], kv.y, a1);
                }
                uint32_t l0, h0, l1, h1;
                UNPK2(l0, h0, a0); UNPK2(l1, h1, a1);
                float acc = (__uint_as_float(l0) + __uint_as_float(h0)) +
                            (__uint_as_float(l1) + __uint_as_float(h1));
                const int j = jt + jc + jj;
                const bool masked = (j <= row) && (j >= row - 7);
                sv[jj] = masked ? -3.4e38f : acc;
            }
            float mc = sv[0];
            #pragma unroll
            for (int jj = 1; jj < 8; ++jj) mc = fmaxf(mc, sv[jj]);
            const float mnew = fmaxf(mrun, mc);
            const float corr = __expf(mrun - mnew);
            lrun *= corr;
            unsigned long long cp; PACK2(cp, corr, corr);
            #pragma unroll
            for (int i = 0; i < 32; ++i) MUL2(o2[i], o2[i], cp);
            mrun = mnew;
            #pragma unroll
            for (int jj = 0; jj < 8; ++jj) {
                const float p = __expf(sv[jj] - mnew);
                lrun += p;
                unsigned long long pp; PACK2(pp, p, p);
                const ulonglong2* vr = &Vs[(jc + jj) * 16];
                #pragma unroll
                for (int i = 0; i < 16; ++i) {
                    ulonglong2 vv = vr[i];
                    FMA2(o2[2*i+0], pp, vv.x, o2[2*i+0]);
                    FMA2(o2[2*i+1], pp, vv.y, o2[2*i+1]);
                }
            }
        }
    }

    const float inv = 1.f / lrun;
    unsigned long long ip; PACK2(ip, inv, inv);
    const int b = bh >> 3, h = bh & 7;
    ulonglong2* Op = (ulonglong2*)(g_O + ((size_t)(b * SS + row) * INNER + h * DHH));
    #pragma unroll
    for (int i = 0; i < 16; ++i) {
        ulonglong2 v;
        MUL2(v.x, o2[2*i+0], ip);
        MUL2(v.y, o2[2*i+1], ip);
        Op[i] = v;
    }
}

// ---------------------------------------------------------------------------
extern "C" void kernel_launch(void* const* d_in, const int* in_sizes, int n_in,
                              void* d_out, int out_size)
{
    const float* x      = (const float*)d_in[0];
    const float* W_qkv  = (const float*)d_in[1];
    const float* u_qkv  = (const float*)d_in[2];
    const float* sg_qkv = (const float*)d_in[3];
    const float* W_out  = (const float*)d_in[4];
    const float* b_out  = (const float*)d_in[5];
    const float* u_out  = (const float*)d_in[6];
    const float* sg_out = (const float*)d_in[7];
    const float* temp   = (const float*)d_in[8];
    float* out = (float*)d_out;

    sn_zero_kernel<<<1, 32>>>();
    sn1_kernel<<<NQKV / 8, 256>>>(W_qkv, u_qkv, DD, 0);
    sn2_kernel<<<DD / 64, 256>>>(W_qkv, NQKV, DD, 0);
    sn1_kernel<<<INNER / 8, 256>>>(W_out, u_out, DD, 1);
    sn2_kernel<<<DD / 64, 256>>>(W_out, INNER, DD, 1);
    sn_fin_kernel<<<1, 32>>>(sg_qkv, sg_out);

    gemm_mma_kernel<0><<<dim3(NQKV / 128, MTOT / 128), 256>>>(x, W_qkv, nullptr, nullptr,
                                                              NQKV, DD, 0);
    attn_kernel<<<dim3(BB * HH, SS / 128), 128>>>(temp);
    gemm_mma_kernel<1><<<dim3(DD / 128, MTOT / 128), 256>>>(nullptr, W_out, b_out, out,
                                                            DD, INNER, 1);
}